// round 16
// baseline (speedup 1.0000x reference)
#include <cuda_runtime.h>
#include <cuda_fp16.h>
#include <cstdint>

// ---------------- Problem constants ----------------
#define B_    32
#define CIN   192
#define T_    256
#define V_    21
#define H_    3
#define COUT  192
#define OUTD  (H_*COUT)        // 576
#define NROWS (B_*T_*V_)       // 172032
#define PPB   (T_*V_)          // 5376

// ---------------- GEMM tiling ----------------
#define MT    256              // M tile (672 blocks)
#define NTC   64               // N chunk (576 = 9*64); 3 chunks per head
#define NCH   9
#define AST   200              // A smem row stride (halves)
#define BST   200              // B smem row stride (halves)
#define GTHREADS 512
#define SMEM_A_BYTES (MT*AST*2)          // 102400
#define SMEM_B_BYTES (NTC*BST*2)         // 25600
#define SMEM_S_OFF   (SMEM_A_BYTES + 2*SMEM_B_BYTES)       // 153600
// s1g[576] s2g[576] ssP[2][256] stP[2][256]
#define GEMM_SMEM    (SMEM_S_OFF + (576*2 + 256*4) * 4)    // 162304

// ---------------- Device scratch ----------------
__device__ __half g_projh[(size_t)NROWS * OUTD];  // 198 MB (fp16 intermediate)
__device__ __half g_Xh[(size_t)NROWS * CIN];      // 66 MB: x transposed+fp16
__device__ __half g_Wh[OUTD * CIN];               // W fp16
__device__ float  g_ss[(size_t)NROWS * H_];       // logits (src)
__device__ float  g_st[(size_t)NROWS * H_];       // logits (tgt)

// ---------------- helpers ----------------
__device__ __forceinline__ uint32_t smem_u32(const void* p) {
    uint32_t a;
    asm("{ .reg .u64 t; cvta.to.shared.u64 t, %1; cvt.u32.u64 %0, t; }"
        : "=r"(a) : "l"(p));
    return a;
}
__device__ __forceinline__ void cp_async16(uint32_t dst, const void* src) {
    asm volatile("cp.async.cg.shared.global [%0], [%1], 16;"
                 :: "r"(dst), "l"(src) : "memory");
}
#define CP_COMMIT() asm volatile("cp.async.commit_group;" ::: "memory")
#define CP_WAIT0()  asm volatile("cp.async.wait_group 0;" ::: "memory")

__device__ __forceinline__ void ldmat_x4(uint32_t* r, uint32_t addr) {
    asm volatile("ldmatrix.sync.aligned.m8n8.x4.shared.b16 {%0,%1,%2,%3}, [%4];"
                 : "=r"(r[0]), "=r"(r[1]), "=r"(r[2]), "=r"(r[3]) : "r"(addr));
}
__device__ __forceinline__ void mma_f16(float* d, const uint32_t* a,
                                        uint32_t b0, uint32_t b1) {
    asm volatile(
        "mma.sync.aligned.m16n8k16.row.col.f32.f16.f16.f32 "
        "{%0,%1,%2,%3}, {%4,%5,%6,%7}, {%8,%9}, {%0,%1,%2,%3};"
        : "+f"(d[0]), "+f"(d[1]), "+f"(d[2]), "+f"(d[3])
        : "r"(a[0]), "r"(a[1]), "r"(a[2]), "r"(a[3]), "r"(b0), "r"(b1));
}

// ---------------- Kernel 0a: transpose+convert x -> g_Xh[(b,p)][c] fp16 ----------------
__global__ __launch_bounds__(256) void cvtX_kernel(const float* __restrict__ x) {
    __shared__ float tile[32][33];
    const int b  = blockIdx.z;
    const int c0 = blockIdx.y * 32;
    const int p0 = blockIdx.x * 32;
    const int tx = threadIdx.x;     // 32
    const int ty = threadIdx.y;     // 8
    const float* xb = x + (size_t)b * CIN * PPB;
    #pragma unroll
    for (int k = 0; k < 4; k++)
        tile[ty + k * 8][tx] = xb[(size_t)(c0 + ty + k * 8) * PPB + p0 + tx];
    __syncthreads();
    __half* xo = g_Xh + ((size_t)b * PPB + p0) * CIN + c0;
    #pragma unroll
    for (int k = 0; k < 4; k++)
        xo[(size_t)(ty + k * 8) * CIN + tx] = __float2half_rn(tile[tx][ty + k * 8]);
}

// ---------------- Kernel 0b: convert W -> fp16 ----------------
__global__ __launch_bounds__(256) void cvtW_kernel(const float* __restrict__ W) {
    int i = blockIdx.x * blockDim.x + threadIdx.x;
    if (i < OUTD * CIN) g_Wh[i] = __float2half_rn(W[i]);
}

// ---------------- Kernel 1: fp16 mma GEMM + fused logits (M256, 16 warps) ----------------
__global__ __launch_bounds__(GTHREADS, 1) void gemm_kernel(
    const float* __restrict__ ssrc, const float* __restrict__ stgt) {
    extern __shared__ char smem[];
    const uint32_t sA = smem_u32(smem);
    const uint32_t sB = sA + SMEM_A_BYTES;
    float* s1g = (float*)(smem + SMEM_S_OFF);         // [576]
    float* s2g = s1g + OUTD;                          // [576]
    float* ssP = s2g + OUTD;                          // [2][256]
    float* stP = ssP + 512;                           // [2][256]

    const int tid   = threadIdx.x;
    const int warp  = tid >> 5;
    const int lane  = tid & 31;
    const int mwarp = warp & 7;     // 0..7 -> M32 slice
    const int nwarp = warp >> 3;    // 0..1 -> N32 slice
    const int g     = lane >> 2;
    const int kq    = lane & 3;

    const size_t m0 = (size_t)blockIdx.x * MT;

    // ---- A tile + score vectors + B chunk 0 ----
    for (int i = tid; i < MT * 24; i += GTHREADS) {
        int r = i / 24, s = i % 24;
        cp_async16(sA + r * (AST * 2) + s * 16, g_Xh + (m0 + r) * CIN + s * 8);
    }
    for (int i = tid; i < NTC * 24; i += GTHREADS) {
        int r = i / 24, s = i % 24;
        cp_async16(sB + r * (BST * 2) + s * 16, g_Wh + (size_t)r * CIN + s * 8);
    }
    for (int i = tid; i < OUTD / 4; i += GTHREADS) {
        ((float4*)s1g)[i] = ((const float4*)ssrc)[i];
        ((float4*)s2g)[i] = ((const float4*)stgt)[i];
    }
    CP_COMMIT();
    CP_WAIT0();
    __syncthreads();

    const int aRow = mwarp * 32 + (lane & 15);
    const uint32_t aBase = sA + aRow * (AST * 2) + ((lane >> 4) * 8) * 2;
    const int bN   = (lane & 7) + ((lane >> 4) << 3);
    const uint32_t bKof = (((lane >> 3) & 1) * 8) * 2;

    float lss[4], lst[4];   // per-head logit partials: idx = m*2 + half(row+8)

    for (int ch = 0; ch < NCH; ch++) {
        if ((ch % 3) == 0) {
            #pragma unroll
            for (int i = 0; i < 4; i++) { lss[i] = 0.f; lst[i] = 0.f; }
        }
        if (ch + 1 < NCH) {
            uint32_t dstb = sB + ((ch + 1) & 1) * SMEM_B_BYTES;
            const __half* src = g_Wh + (size_t)(ch + 1) * NTC * CIN;
            for (int i = tid; i < NTC * 24; i += GTHREADS) {
                int r = i / 24, s = i % 24;
                cp_async16(dstb + r * (BST * 2) + s * 16, src + (size_t)r * CIN + s * 8);
            }
            CP_COMMIT();
        }

        const uint32_t sBc = sB + (ch & 1) * SMEM_B_BYTES;
        uint32_t bBase[2];
        #pragma unroll
        for (int i2 = 0; i2 < 2; i2++)
            bBase[i2] = sBc + (nwarp * 32 + i2 * 16 + bN) * (BST * 2) + bKof;

        float acc[4][2][4];
        #pragma unroll
        for (int f = 0; f < 4; f++)
            #pragma unroll
            for (int m = 0; m < 2; m++)
                #pragma unroll
                for (int q = 0; q < 4; q++) acc[f][m][q] = 0.0f;

        #pragma unroll 4
        for (int kk = 0; kk < 12; kk++) {
            const uint32_t kof = kk * 32;
            uint32_t a[2][4], br[2][4];
            ldmat_x4(a[0], aBase + kof);
            ldmat_x4(a[1], aBase + 16 * (AST * 2) + kof);
            #pragma unroll
            for (int i2 = 0; i2 < 2; i2++)
                ldmat_x4(br[i2], bBase[i2] + kof);
            #pragma unroll
            for (int i2 = 0; i2 < 2; i2++)
                #pragma unroll
                for (int t = 0; t < 2; t++) {
                    const int f = i2 * 2 + t;
                    mma_f16(acc[f][0], a[0], br[i2][t * 2], br[i2][t * 2 + 1]);
                    mma_f16(acc[f][1], a[1], br[i2][t * 2], br[i2][t * 2 + 1]);
                }
        }

        // ---- fused logits: fold acc against ssrc/stgt (fp32) ----
        {
            const float* s1c = s1g + ch * NTC + nwarp * 32 + 2 * kq;
            const float* s2c = s2g + ch * NTC + nwarp * 32 + 2 * kq;
            #pragma unroll
            for (int f = 0; f < 4; f++) {
                const int nOf = (f >> 1) * 16 + (f & 1) * 8;
                float sa0 = s1c[nOf], sa1 = s1c[nOf + 1];
                float sb0 = s2c[nOf], sb1 = s2c[nOf + 1];
                #pragma unroll
                for (int m = 0; m < 2; m++) {
                    lss[m * 2 + 0] = fmaf(acc[f][m][0], sa0, fmaf(acc[f][m][1], sa1, lss[m * 2 + 0]));
                    lss[m * 2 + 1] = fmaf(acc[f][m][2], sa0, fmaf(acc[f][m][3], sa1, lss[m * 2 + 1]));
                    lst[m * 2 + 0] = fmaf(acc[f][m][0], sb0, fmaf(acc[f][m][1], sb1, lst[m * 2 + 0]));
                    lst[m * 2 + 1] = fmaf(acc[f][m][2], sb0, fmaf(acc[f][m][3], sb1, lst[m * 2 + 1]));
                }
            }
        }

        // ---- epilogue: warp writes its M32 x N32 block as fp16 ----
        {
            const int n0c = ch * NTC + nwarp * 32;
            #pragma unroll
            for (int m = 0; m < 2; m++) {
                __half* r0p = g_projh + (m0 + mwarp * 32 + m * 16 + g) * OUTD + n0c + 2 * kq;
                __half* r1p = r0p + 8 * OUTD;
                #pragma unroll
                for (int f = 0; f < 4; f++) {
                    const int nOf = (f >> 1) * 16 + (f & 1) * 8;
                    *(__half2*)(r0p + nOf) = __floats2half2_rn(acc[f][m][0], acc[f][m][1]);
                    *(__half2*)(r1p + nOf) = __floats2half2_rn(acc[f][m][2], acc[f][m][3]);
                }
            }
        }

        // ---- head boundary: reduce + write logits ----
        if ((ch % 3) == 2) {
            #pragma unroll
            for (int i = 0; i < 4; i++) {
                lss[i] += __shfl_down_sync(0xffffffffu, lss[i], 1);
                lss[i] += __shfl_down_sync(0xffffffffu, lss[i], 2);
                lst[i] += __shfl_down_sync(0xffffffffu, lst[i], 1);
                lst[i] += __shfl_down_sync(0xffffffffu, lst[i], 2);
            }
            if (kq == 0) {
                #pragma unroll
                for (int i = 0; i < 4; i++) {
                    int row = mwarp * 32 + (i >> 1) * 16 + g + (i & 1) * 8;
                    ssP[nwarp * 256 + row] = lss[i];
                    stP[nwarp * 256 + row] = lst[i];
                }
            }
            __syncthreads();
            if (tid < 256) {
                const int h = ch / 3;
                g_ss[(m0 + tid) * H_ + h] = ssP[tid] + ssP[256 + tid];
                g_st[(m0 + tid) * H_ + h] = stP[tid] + stP[256 + tid];
            }
        }

        if (ch + 1 < NCH) CP_WAIT0();
        __syncthreads();
    }
}

// ---------------- Kernel 2: attention + aggregation + skip/mean ----------------
#define NTHREADS 288
#define WSTRIDE  22
extern __shared__ char asmem_raw[];

__global__ __launch_bounds__(NTHREADS, 4) void gat_attn_kernel(
    const float* __restrict__ A,      // (H, V, V)
    float* __restrict__ out)          // (NROWS, COUT) flat
{
    __half* projh = (__half*)asmem_raw;                 // [V][OUTD] halves
    float*  fbase = (float*)(asmem_raw + ((V_ * OUTD * 2 + 15) & ~15));
    float* ss_s = fbase;                  // [64]
    float* st_s = ss_s + 64;              // [64]
    float* w_s  = st_s + 64;              // [63*21 -> pad 1324]
    float* wsum = w_s + 1324;             // [21][WSTRIDE]

    const int bp  = blockIdx.x;
    const int tid = threadIdx.x;

    // Phase 1: load proj tile + precomputed logits
    {
        const uint4* src = (const uint4*)(g_projh + (size_t)bp * V_ * OUTD);
        uint4* dst = (uint4*)projh;
        for (int i = tid; i < V_ * OUTD * 2 / 16; i += NTHREADS)
            dst[i] = src[i];
        if (tid < 63) {
            ss_s[tid] = g_ss[bp * 63 + tid];   // index p = v*3+h
            st_s[tid] = g_st[bp * 63 + tid];
        }
    }
    __syncthreads();

    // Phase 3: masked softmax, one (h,i) row per thread
    if (tid < 63) {
        const int h = tid / 21;
        const int i = tid % 21;
        const float ssi = ss_s[i * 3 + h];
        const float* Arow = A + (h * V_ + i) * V_;
        float sc[21];
        float mx = -1e30f;
        #pragma unroll
        for (int j = 0; j < V_; j++) {
            float a = Arow[j];
            float s = ssi + st_s[j * 3 + h];
            s = (s >= 0.f) ? s : 0.2f * s;
            s += a;
            sc[j] = (a != 0.f) ? s : -1e30f;
            mx = fmaxf(mx, sc[j]);
        }
        float sum = 0.f;
        #pragma unroll
        for (int j = 0; j < V_; j++) {
            float e = (sc[j] > -1e29f) ? __expf(sc[j] - mx) : 0.f;
            sc[j] = e;
            sum += e;
        }
        float inv = 1.0f / sum;
        #pragma unroll
        for (int j = 0; j < V_; j++)
            w_s[tid * V_ + j] = sc[j] * inv;
    }
    __syncthreads();

    // Phase 3.5: pre-sum the 3 attention rows feeding each output row
    for (int idx = tid; idx < V_ * V_; idx += NTHREADS) {
        int r = idx / V_, j = idx % V_;
        int h = r / 7, q = r % 7;
        int i0 = h * 21 + 3 * q;
        wsum[r * WSTRIDE + j] = w_s[(i0 + 0) * V_ + j]
                              + w_s[(i0 + 1) * V_ + j]
                              + w_s[(i0 + 2) * V_ + j];
    }
    __syncthreads();

    // Phase 4: aggregation + skip + mean — (h, column-pair) per thread
    {
        const int h  = tid / 96;        // 0..2
        const int c  = (tid % 96) * 2;  // even column
        float* op = out + (size_t)bp * V_ * COUT;

        __half2 p2[21];                 // this head's column-pair, all 21 rows
        #pragma unroll
        for (int j = 0; j < V_; j++)
            p2[j] = *(const __half2*)(projh + j * OUTD + h * COUT + c);

        #pragma unroll
        for (int q = 0; q < 7; q++) {
            const int r = h * 7 + q;
            const float2* ws2 = (const float2*)(wsum + r * WSTRIDE);
            float2 k0 = __half22float2(*(const __half2*)(projh + r * OUTD + c));
            float2 k1 = __half22float2(*(const __half2*)(projh + r * OUTD + COUT + c));
            float2 k2 = __half22float2(*(const __half2*)(projh + r * OUTD + 2 * COUT + c));
            float ax = k0.x + k1.x + k2.x;
            float ay = k0.y + k1.y + k2.y;
            #pragma unroll
            for (int jp = 0; jp < 10; jp++) {
                float2 wv = ws2[jp];
                float2 pa = __half22float2(p2[2 * jp]);
                float2 pb = __half22float2(p2[2 * jp + 1]);
                ax = fmaf(wv.x, pa.x, ax);
                ay = fmaf(wv.x, pa.y, ay);
                ax = fmaf(wv.y, pb.x, ax);
                ay = fmaf(wv.y, pb.y, ay);
            }
            {
                float wj = wsum[r * WSTRIDE + 20];
                float2 pv = __half22float2(p2[20]);
                ax = fmaf(wj, pv.x, ax);
                ay = fmaf(wj, pv.y, ay);
            }
            *(float2*)(op + r * COUT + c) = make_float2(ax * (1.0f / 3.0f),
                                                        ay * (1.0f / 3.0f));
        }
    }
}

// ---------------- Launch ----------------
extern "C" void kernel_launch(void* const* d_in, const int* in_sizes, int n_in,
                              void* d_out, int out_size) {
    const float* x    = (const float*)d_in[0];
    const float* A    = (const float*)d_in[1];
    const float* W    = (const float*)d_in[2];
    const float* ssrc = (const float*)d_in[3];
    const float* stgt = (const float*)d_in[4];
    float* out = (float*)d_out;

    cudaFuncSetAttribute(gemm_kernel,
                         cudaFuncAttributeMaxDynamicSharedMemorySize, GEMM_SMEM);
    const int attn_smem = ((V_ * OUTD * 2 + 15) & ~15)
                        + (64 + 64 + 1324 + V_ * WSTRIDE) * (int)sizeof(float);
    cudaFuncSetAttribute(gat_attn_kernel,
                         cudaFuncAttributeMaxDynamicSharedMemorySize, attn_smem);

    cvtX_kernel<<<dim3(PPB / 32, CIN / 32, B_), dim3(32, 8)>>>(x);
    cvtW_kernel<<<(OUTD * CIN + 255) / 256, 256>>>(W);
    gemm_kernel<<<NROWS / MT, GTHREADS, GEMM_SMEM>>>(ssrc, stgt);
    gat_attn_kernel<<<B_ * T_, NTHREADS, attn_smem>>>(A, out);
}

// round 17
// speedup vs baseline: 1.1262x; 1.1262x over previous
#include <cuda_runtime.h>
#include <cuda_fp16.h>
#include <cstdint>

// ---------------- Problem constants ----------------
#define B_    32
#define CIN   192
#define T_    256
#define V_    21
#define H_    3
#define COUT  192
#define OUTD  (H_*COUT)        // 576
#define NROWS (B_*T_*V_)       // 172032
#define PPB   (T_*V_)          // 5376

// ---------------- GEMM tiling (R15 config) ----------------
#define MT    128              // M tile (1344 blocks)
#define NTC   64               // N chunk (576 = 9*64); 3 chunks per head
#define NCH   9
#define AST   200              // A smem row stride (halves)
#define BST   200              // B smem row stride (halves)
#define GTHREADS 256
#define SMEM_A_BYTES (MT*AST*2)          // 51200
#define SMEM_B_BYTES (NTC*BST*2)         // 25600
#define SMEM_S_OFF   (SMEM_A_BYTES + 2*SMEM_B_BYTES)       // 102400
// s1g[576] s2g[576] ssP[2][128] stP[2][128]
#define GEMM_SMEM    (SMEM_S_OFF + (576*2 + 128*4) * 4)    // 109056

// ---------------- Device scratch ----------------
__device__ __half g_projh[(size_t)NROWS * OUTD];  // 198 MB (fp16 intermediate)
__device__ __half g_Xh[(size_t)NROWS * CIN];      // 66 MB: x transposed+fp16
__device__ __half g_Wh[OUTD * CIN];               // W fp16
__device__ float  g_ss[(size_t)NROWS * H_];       // logits (src)
__device__ float  g_st[(size_t)NROWS * H_];       // logits (tgt)

// ---------------- helpers ----------------
__device__ __forceinline__ uint32_t smem_u32(const void* p) {
    uint32_t a;
    asm("{ .reg .u64 t; cvta.to.shared.u64 t, %1; cvt.u32.u64 %0, t; }"
        : "=r"(a) : "l"(p));
    return a;
}
__device__ __forceinline__ void cp_async16(uint32_t dst, const void* src) {
    asm volatile("cp.async.cg.shared.global [%0], [%1], 16;"
                 :: "r"(dst), "l"(src) : "memory");
}
#define CP_COMMIT() asm volatile("cp.async.commit_group;" ::: "memory")
#define CP_WAIT0()  asm volatile("cp.async.wait_group 0;" ::: "memory")

__device__ __forceinline__ void ldmat_x4(uint32_t* r, uint32_t addr) {
    asm volatile("ldmatrix.sync.aligned.m8n8.x4.shared.b16 {%0,%1,%2,%3}, [%4];"
                 : "=r"(r[0]), "=r"(r[1]), "=r"(r[2]), "=r"(r[3]) : "r"(addr));
}
__device__ __forceinline__ void mma_f16(float* d, const uint32_t* a,
                                        uint32_t b0, uint32_t b1) {
    asm volatile(
        "mma.sync.aligned.m16n8k16.row.col.f32.f16.f16.f32 "
        "{%0,%1,%2,%3}, {%4,%5,%6,%7}, {%8,%9}, {%0,%1,%2,%3};"
        : "+f"(d[0]), "+f"(d[1]), "+f"(d[2]), "+f"(d[3])
        : "r"(a[0]), "r"(a[1]), "r"(a[2]), "r"(a[3]), "r"(b0), "r"(b1));
}

// ---------------- Kernel 0a: transpose+convert x -> g_Xh[(b,p)][c] fp16 ----------------
__global__ __launch_bounds__(256) void cvtX_kernel(const float* __restrict__ x) {
    __shared__ float tile[32][33];
    const int b  = blockIdx.z;
    const int c0 = blockIdx.y * 32;
    const int p0 = blockIdx.x * 32;
    const int tx = threadIdx.x;     // 32
    const int ty = threadIdx.y;     // 8
    const float* xb = x + (size_t)b * CIN * PPB;
    #pragma unroll
    for (int k = 0; k < 4; k++)
        tile[ty + k * 8][tx] = xb[(size_t)(c0 + ty + k * 8) * PPB + p0 + tx];
    __syncthreads();
    __half* xo = g_Xh + ((size_t)b * PPB + p0) * CIN + c0;
    #pragma unroll
    for (int k = 0; k < 4; k++)
        xo[(size_t)(ty + k * 8) * CIN + tx] = __float2half_rn(tile[tx][ty + k * 8]);
}

// ---------------- Kernel 0b: convert W -> fp16 ----------------
__global__ __launch_bounds__(256) void cvtW_kernel(const float* __restrict__ W) {
    int i = blockIdx.x * blockDim.x + threadIdx.x;
    if (i < OUTD * CIN) g_Wh[i] = __float2half_rn(W[i]);
}

// ---------------- Kernel 1: fp16 mma GEMM + fused logits (R15) ----------------
__global__ __launch_bounds__(GTHREADS, 2) void gemm_kernel(
    const float* __restrict__ ssrc, const float* __restrict__ stgt) {
    extern __shared__ char smem[];
    const uint32_t sA = smem_u32(smem);
    const uint32_t sB = sA + SMEM_A_BYTES;
    float* s1g = (float*)(smem + SMEM_S_OFF);         // [576]
    float* s2g = s1g + OUTD;                          // [576]
    float* ssP = s2g + OUTD;                          // [2][128]
    float* stP = ssP + 256;                           // [2][128]

    const int tid   = threadIdx.x;
    const int warp  = tid >> 5;
    const int lane  = tid & 31;
    const int mwarp = warp & 3;     // 0..3 -> M32 slice
    const int nwarp = warp >> 2;    // 0..1 -> N32 slice
    const int g     = lane >> 2;
    const int kq    = lane & 3;

    const size_t m0 = (size_t)blockIdx.x * MT;

    // ---- A tile + score vectors + B chunk 0 ----
    for (int i = tid; i < MT * 24; i += GTHREADS) {
        int r = i / 24, s = i % 24;
        cp_async16(sA + r * (AST * 2) + s * 16, g_Xh + (m0 + r) * CIN + s * 8);
    }
    for (int i = tid; i < NTC * 24; i += GTHREADS) {
        int r = i / 24, s = i % 24;
        cp_async16(sB + r * (BST * 2) + s * 16, g_Wh + (size_t)r * CIN + s * 8);
    }
    for (int i = tid; i < OUTD / 4; i += GTHREADS) {
        ((float4*)s1g)[i] = ((const float4*)ssrc)[i];
        ((float4*)s2g)[i] = ((const float4*)stgt)[i];
    }
    CP_COMMIT();
    CP_WAIT0();
    __syncthreads();

    const int aRow = mwarp * 32 + (lane & 15);
    const uint32_t aBase = sA + aRow * (AST * 2) + ((lane >> 4) * 8) * 2;
    const int bN   = (lane & 7) + ((lane >> 4) << 3);
    const uint32_t bKof = (((lane >> 3) & 1) * 8) * 2;

    float lss[4], lst[4];   // per-head logit partials: idx = m*2 + half(row+8)

    for (int ch = 0; ch < NCH; ch++) {
        if ((ch % 3) == 0) {
            #pragma unroll
            for (int i = 0; i < 4; i++) { lss[i] = 0.f; lst[i] = 0.f; }
        }
        if (ch + 1 < NCH) {
            uint32_t dstb = sB + ((ch + 1) & 1) * SMEM_B_BYTES;
            const __half* src = g_Wh + (size_t)(ch + 1) * NTC * CIN;
            for (int i = tid; i < NTC * 24; i += GTHREADS) {
                int r = i / 24, s = i % 24;
                cp_async16(dstb + r * (BST * 2) + s * 16, src + (size_t)r * CIN + s * 8);
            }
            CP_COMMIT();
        }

        const uint32_t sBc = sB + (ch & 1) * SMEM_B_BYTES;
        uint32_t bBase[2];
        #pragma unroll
        for (int i2 = 0; i2 < 2; i2++)
            bBase[i2] = sBc + (nwarp * 32 + i2 * 16 + bN) * (BST * 2) + bKof;

        float acc[4][2][4];
        #pragma unroll
        for (int f = 0; f < 4; f++)
            #pragma unroll
            for (int m = 0; m < 2; m++)
                #pragma unroll
                for (int q = 0; q < 4; q++) acc[f][m][q] = 0.0f;

        #pragma unroll 4
        for (int kk = 0; kk < 12; kk++) {
            const uint32_t kof = kk * 32;
            uint32_t a[2][4], br[2][4];
            ldmat_x4(a[0], aBase + kof);
            ldmat_x4(a[1], aBase + 16 * (AST * 2) + kof);
            #pragma unroll
            for (int i2 = 0; i2 < 2; i2++)
                ldmat_x4(br[i2], bBase[i2] + kof);
            #pragma unroll
            for (int i2 = 0; i2 < 2; i2++)
                #pragma unroll
                for (int t = 0; t < 2; t++) {
                    const int f = i2 * 2 + t;
                    mma_f16(acc[f][0], a[0], br[i2][t * 2], br[i2][t * 2 + 1]);
                    mma_f16(acc[f][1], a[1], br[i2][t * 2], br[i2][t * 2 + 1]);
                }
        }

        // ---- fused logits: fold acc against ssrc/stgt (fp32) ----
        {
            const float* s1c = s1g + ch * NTC + nwarp * 32 + 2 * kq;
            const float* s2c = s2g + ch * NTC + nwarp * 32 + 2 * kq;
            #pragma unroll
            for (int f = 0; f < 4; f++) {
                const int nOf = (f >> 1) * 16 + (f & 1) * 8;
                float sa0 = s1c[nOf], sa1 = s1c[nOf + 1];
                float sb0 = s2c[nOf], sb1 = s2c[nOf + 1];
                #pragma unroll
                for (int m = 0; m < 2; m++) {
                    lss[m * 2 + 0] = fmaf(acc[f][m][0], sa0, fmaf(acc[f][m][1], sa1, lss[m * 2 + 0]));
                    lss[m * 2 + 1] = fmaf(acc[f][m][2], sa0, fmaf(acc[f][m][3], sa1, lss[m * 2 + 1]));
                    lst[m * 2 + 0] = fmaf(acc[f][m][0], sb0, fmaf(acc[f][m][1], sb1, lst[m * 2 + 0]));
                    lst[m * 2 + 1] = fmaf(acc[f][m][2], sb0, fmaf(acc[f][m][3], sb1, lst[m * 2 + 1]));
                }
            }
        }

        // ---- epilogue: warp writes its M32 x N32 block as fp16 ----
        {
            const int n0c = ch * NTC + nwarp * 32;
            #pragma unroll
            for (int m = 0; m < 2; m++) {
                __half* r0p = g_projh + (m0 + mwarp * 32 + m * 16 + g) * OUTD + n0c + 2 * kq;
                __half* r1p = r0p + 8 * OUTD;
                #pragma unroll
                for (int f = 0; f < 4; f++) {
                    const int nOf = (f >> 1) * 16 + (f & 1) * 8;
                    *(__half2*)(r0p + nOf) = __floats2half2_rn(acc[f][m][0], acc[f][m][1]);
                    *(__half2*)(r1p + nOf) = __floats2half2_rn(acc[f][m][2], acc[f][m][3]);
                }
            }
        }

        // ---- head boundary: reduce + write logits ----
        if ((ch % 3) == 2) {
            #pragma unroll
            for (int i = 0; i < 4; i++) {
                lss[i] += __shfl_down_sync(0xffffffffu, lss[i], 1);
                lss[i] += __shfl_down_sync(0xffffffffu, lss[i], 2);
                lst[i] += __shfl_down_sync(0xffffffffu, lst[i], 1);
                lst[i] += __shfl_down_sync(0xffffffffu, lst[i], 2);
            }
            if (kq == 0) {
                #pragma unroll
                for (int i = 0; i < 4; i++) {
                    int row = mwarp * 32 + (i >> 1) * 16 + g + (i & 1) * 8;
                    ssP[nwarp * 128 + row] = lss[i];
                    stP[nwarp * 128 + row] = lst[i];
                }
            }
            __syncthreads();
            if (tid < 128) {
                const int h = ch / 3;
                g_ss[(m0 + tid) * H_ + h] = ssP[tid] + ssP[128 + tid];
                g_st[(m0 + tid) * H_ + h] = stP[tid] + stP[128 + tid];
            }
        }

        if (ch + 1 < NCH) CP_WAIT0();
        __syncthreads();
    }
}

// ---------------- Kernel 2: attention + aggregation + skip/mean ----------------
#define NTHREADS 288
#define WSTRIDE  22
extern __shared__ char asmem_raw[];

__global__ __launch_bounds__(NTHREADS, 4) void gat_attn_kernel(
    const float* __restrict__ A,      // (H, V, V)
    float* __restrict__ out)          // (NROWS, COUT) flat
{
    float* fbase = (float*)asmem_raw;
    float* ss_s = fbase;                  // [64]
    float* st_s = ss_s + 64;              // [64]
    float* w_s  = st_s + 64;              // [63*21 -> pad 1324]
    float* wsum = w_s + 1324;             // [21][WSTRIDE]

    const int bp  = blockIdx.x;
    const int tid = threadIdx.x;
    const __half* projg = g_projh + (size_t)bp * V_ * OUTD;

    // Phase 1: load precomputed logits
    if (tid < 63) {
        ss_s[tid] = g_ss[bp * 63 + tid];   // index p = v*3+h
        st_s[tid] = g_st[bp * 63 + tid];
    }
    __syncthreads();

    // Phase 3: masked softmax, one (h,i) row per thread
    if (tid < 63) {
        const int h = tid / 21;
        const int i = tid % 21;
        const float ssi = ss_s[i * 3 + h];
        const float* Arow = A + (h * V_ + i) * V_;
        float sc[21];
        float mx = -1e30f;
        #pragma unroll
        for (int j = 0; j < V_; j++) {
            float a = Arow[j];
            float s = ssi + st_s[j * 3 + h];
            s = (s >= 0.f) ? s : 0.2f * s;
            s += a;
            sc[j] = (a != 0.f) ? s : -1e30f;
            mx = fmaxf(mx, sc[j]);
        }
        float sum = 0.f;
        #pragma unroll
        for (int j = 0; j < V_; j++) {
            float e = (sc[j] > -1e29f) ? __expf(sc[j] - mx) : 0.f;
            sc[j] = e;
            sum += e;
        }
        float inv = 1.0f / sum;
        #pragma unroll
        for (int j = 0; j < V_; j++)
            w_s[tid * V_ + j] = sc[j] * inv;
    }
    __syncthreads();

    // Phase 3.5: pre-sum the 3 attention rows feeding each output row
    for (int idx = tid; idx < V_ * V_; idx += NTHREADS) {
        int r = idx / V_, j = idx % V_;
        int h = r / 7, q = r % 7;
        int i0 = h * 21 + 3 * q;
        wsum[r * WSTRIDE + j] = w_s[(i0 + 0) * V_ + j]
                              + w_s[(i0 + 1) * V_ + j]
                              + w_s[(i0 + 2) * V_ + j];
    }
    __syncthreads();

    // Phase 4: aggregation + skip + mean — (h, column-pair) per thread,
    // proj read directly from global (coalesced 128B/warp, L1-resident tile)
    {
        const int h  = tid / 96;        // 0..2
        const int c  = (tid % 96) * 2;  // even column
        float* op = out + (size_t)bp * V_ * COUT;

        __half2 p2[21];                 // this head's column-pair, all 21 rows
        #pragma unroll
        for (int j = 0; j < V_; j++)
            p2[j] = *(const __half2*)(projg + j * OUTD + h * COUT + c);

        #pragma unroll
        for (int q = 0; q < 7; q++) {
            const int r = h * 7 + q;
            const float2* ws2 = (const float2*)(wsum + r * WSTRIDE);
            float2 k0 = __half22float2(*(const __half2*)(projg + r * OUTD + c));
            float2 k1 = __half22float2(*(const __half2*)(projg + r * OUTD + COUT + c));
            float2 k2 = __half22float2(*(const __half2*)(projg + r * OUTD + 2 * COUT + c));
            float ax = k0.x + k1.x + k2.x;
            float ay = k0.y + k1.y + k2.y;
            #pragma unroll
            for (int jp = 0; jp < 10; jp++) {
                float2 wv = ws2[jp];
                float2 pa = __half22float2(p2[2 * jp]);
                float2 pb = __half22float2(p2[2 * jp + 1]);
                ax = fmaf(wv.x, pa.x, ax);
                ay = fmaf(wv.x, pa.y, ay);
                ax = fmaf(wv.y, pb.x, ax);
                ay = fmaf(wv.y, pb.y, ay);
            }
            {
                float wj = wsum[r * WSTRIDE + 20];
                float2 pv = __half22float2(p2[20]);
                ax = fmaf(wj, pv.x, ax);
                ay = fmaf(wj, pv.y, ay);
            }
            *(float2*)(op + r * COUT + c) = make_float2(ax * (1.0f / 3.0f),
                                                        ay * (1.0f / 3.0f));
        }
    }
}

// ---------------- Launch ----------------
extern "C" void kernel_launch(void* const* d_in, const int* in_sizes, int n_in,
                              void* d_out, int out_size) {
    const float* x    = (const float*)d_in[0];
    const float* A    = (const float*)d_in[1];
    const float* W    = (const float*)d_in[2];
    const float* ssrc = (const float*)d_in[3];
    const float* stgt = (const float*)d_in[4];
    float* out = (float*)d_out;

    cudaFuncSetAttribute(gemm_kernel,
                         cudaFuncAttributeMaxDynamicSharedMemorySize, GEMM_SMEM);
    const int attn_smem = (64 + 64 + 1324 + V_ * WSTRIDE) * (int)sizeof(float);
    cudaFuncSetAttribute(gat_attn_kernel,
                         cudaFuncAttributeMaxDynamicSharedMemorySize, attn_smem);

    cvtX_kernel<<<dim3(PPB / 32, CIN / 32, B_), dim3(32, 8)>>>(x);
    cvtW_kernel<<<(OUTD * CIN + 255) / 256, 256>>>(W);
    gemm_kernel<<<NROWS / MT, GTHREADS, GEMM_SMEM>>>(ssrc, stgt);
    gat_attn_kernel<<<B_ * T_, NTHREADS, attn_smem>>>(A, out);
}